// round 10
// baseline (speedup 1.0000x reference)
#include <cuda_runtime.h>
#include <cuda_bf16.h>
#include <cstdint>

// ============================ constants ============================
#define NR        200               // number of masks
#define HW        200704            // 448*448
#define NTK       3136              // total K tiles of 64
#define GRID      148
#define NTHREADS  512
#define ROWSTR    144               // bf16 buffer row stride in bytes (conflict-free, proven)
#define BUF_B     (224*ROWSTR)      // 32256 (200 data rows + 24 zero pad)
#define DYN_SMEM  (2*BUF_B)         // 64512
#define NTOUT     28                // upper-tri 32x32 tiles (7x7 grid)
#define NPART     (49*1024)         // slab elements (full 7x7 grid)

__device__ unsigned short g_scratch16[(size_t)GRID * NPART];   // u16 partials (<=1792, exact)
__device__ float g_inter[NR * NR];
__device__ float g_comp[256];
__device__ unsigned g_count;
__device__ unsigned g_gen;

__device__ __constant__ unsigned char TIa[NTOUT] =
    {0,0,0,0,0,0,0, 1,1,1,1,1,1, 2,2,2,2,2, 3,3,3,3, 4,4,4, 5,5, 6};
__device__ __constant__ unsigned char TJa[NTOUT] =
    {0,1,2,3,4,5,6, 1,2,3,4,5,6, 2,3,4,5,6, 3,4,5,6, 4,5,6, 5,6, 6};

// per-warp gram jobs: 12 pairs (A-fragment shared across 2 tj) + 4 singles = 16 (R5-proven)
__device__ __constant__ unsigned char JTI[16] = {0,0,0, 1,1,1, 2,2, 3,3, 4, 5, 0, 2, 4, 6};
__device__ __constant__ unsigned char JT0[16] = {0,2,4, 1,3,5, 2,4, 3,5, 4, 5, 6, 6, 6, 6};
__device__ __constant__ unsigned char JN [16] = {2,2,2, 2,2,2, 2,2, 2,2, 2, 2, 1, 1, 1, 1};

// ============================ helpers ============================
__device__ __forceinline__ uint32_t smem_u32(const void* p) {
    uint32_t a;
    asm("{ .reg .u64 t; cvta.to.shared.u64 t, %1; cvt.u32.u64 %0, t; }"
        : "=r"(a) : "l"(p));
    return a;
}

__device__ __forceinline__ void ldg128(float4& v, const float* p) {
    asm volatile("ld.global.nc.v4.f32 {%0,%1,%2,%3}, [%4];"
                 : "=f"(v.x), "=f"(v.y), "=f"(v.z), "=f"(v.w) : "l"(p));
}

__device__ __forceinline__ void ldsm4(uint32_t* r, uint32_t addr) {
    asm volatile("ldmatrix.sync.aligned.m8n8.x4.shared.b16 {%0,%1,%2,%3}, [%4];"
                 : "=r"(r[0]), "=r"(r[1]), "=r"(r[2]), "=r"(r[3]) : "r"(addr));
}

__device__ __forceinline__ void mma16816(float* d, const uint32_t* a, const uint32_t* b) {
    asm volatile(
        "mma.sync.aligned.m16n8k16.row.col.f32.bf16.bf16.f32 "
        "{%0,%1,%2,%3}, {%4,%5,%6,%7}, {%8,%9}, {%0,%1,%2,%3};"
        : "+f"(d[0]), "+f"(d[1]), "+f"(d[2]), "+f"(d[3])
        : "r"(a[0]), "r"(a[1]), "r"(a[2]), "r"(a[3]), "r"(b[0]), "r"(b[1]));
}

// grid barrier: atomic arrivals, plain-load polling with nanosleep backoff
__device__ __forceinline__ void grid_barrier() {
    __syncthreads();
    if (threadIdx.x == 0) {
        __threadfence();
        unsigned gen = *(volatile unsigned*)&g_gen;
        unsigned arrived = atomicAdd(&g_count, 1u) + 1u;
        if (arrived == GRID) {
            atomicExch(&g_count, 0u);
            __threadfence();
            atomicAdd(&g_gen, 1u);
        } else {
            while (*(volatile unsigned*)&g_gen == gen) __nanosleep(128);
        }
        __threadfence();
    }
    __syncthreads();
}

// STS one converted float4 (4 fp32 -> 4 bf16 = 8 bytes)
__device__ __forceinline__ void sts_bf16(char* smem, int buf_off, int idx, const float4& v) {
    const int row = idx >> 4, c4 = idx & 15;
    __nv_bfloat162 p0 = __floats2bfloat162_rn(v.x, v.y);
    __nv_bfloat162 p1 = __floats2bfloat162_rn(v.z, v.w);
    uint2 w;
    w.x = *reinterpret_cast<uint32_t*>(&p0);
    w.y = *reinterpret_cast<uint32_t*>(&p1);
    *reinterpret_cast<uint2*>(smem + buf_off + (size_t)row * ROWSTR + c4 * 8) = w;
}

// ============================ fused kernel ============================
__global__ __launch_bounds__(NTHREADS, 1)
void fused_kernel(const float* __restrict__ seg,
                  const float* __restrict__ scores,
                  const int* __restrict__ labels,
                  float* __restrict__ out) {
    extern __shared__ char smem[];
    const uint32_t sbase = smem_u32(smem);
    const int tid = threadIdx.x;
    const int wid = tid >> 5;
    const int lid = tid & 31;
    const int bid = blockIdx.x;

    // ================= phase 1: split-K Gram (bf16 mma, LDG-direct, no fp32 stage) =================
    {
        const int t0 = (bid * NTK) / GRID;
        const int t1 = ((bid + 1) * NTK) / GRID;

        // zero pad rows 200..223 of both bf16 buffers (written once)
        for (int i = tid; i < (24 * ROWSTR) / 4; i += NTHREADS) {
            *reinterpret_cast<uint32_t*>(smem + 200 * ROWSTR + i * 4) = 0u;
            *reinterpret_cast<uint32_t*>(smem + BUF_B + 200 * ROWSTR + i * 4) = 0u;
        }

        const int ti  = JTI[wid];
        const int tj0 = JT0[wid];
        const int njt = JN[wid];

        float acc[2][2][4][4];   // [tile][m-half][n-quarter][regs] = 64 regs
        #pragma unroll
        for (int a = 0; a < 2; a++)
            #pragma unroll
            for (int b = 0; b < 2; b++)
                #pragma unroll
                for (int c = 0; c < 4; c++)
                    #pragma unroll
                    for (int d = 0; d < 4; d++) acc[a][b][c][d] = 0.f;

        const uint32_t aoff = (uint32_t)(lid & 15) * ROWSTR + (uint32_t)((lid >> 4) << 4);
        const uint32_t boff = (uint32_t)(((lid >> 4) << 3) + (lid & 7)) * ROWSTR
                            + (uint32_t)(((lid >> 3) & 1) << 4);
        const uint32_t arow = (uint32_t)(ti * 32) * ROWSTR + aoff;

        // per-thread load coords (fixed across tiles): idx = tid + it*512, it 0..6
        // prologue: LDG -> cvt -> STS tile t0 into buf0
        {
            const float* base = seg + (size_t)t0 * 64;
            #pragma unroll
            for (int it = 0; it < 7; it++) {
                const int idx = tid + it * NTHREADS;
                if (idx < 3200) {
                    float4 v;
                    ldg128(v, base + (size_t)(idx >> 4) * HW + (idx & 15) * 4);
                    sts_bf16(smem, (t0 & 1) * BUF_B, idx, v);
                }
            }
        }
        __syncthreads();

        for (int t = t0; t < t1; t++) {
            const bool more = (t + 1 < t1);
            const int nbuf = ((t + 1) & 1) * BUF_B;
            const uint32_t buf = sbase + (uint32_t)((t & 1) * BUF_B);
            const float* nb = seg + (size_t)(t + 1) * 64;

            // LDG batch A for tile t+1 (it 0..3) — issued early, consumed after ksteps 0,1
            float4 pfA[4];
            if (more) {
                #pragma unroll
                for (int it = 0; it < 4; it++) {
                    const int idx = tid + it * NTHREADS;
                    ldg128(pfA[it], nb + (size_t)(idx >> 4) * HW + (idx & 15) * 4);
                }
            }

            // ---- ksteps 0,1 ----
            #pragma unroll
            for (int ks = 0; ks < 2; ks++) {
                const uint32_t koff = (uint32_t)ks * 32;
                uint32_t afr[2][4];
                ldsm4(afr[0], buf + arow + koff);
                ldsm4(afr[1], buf + arow + koff + 16 * ROWSTR);
                #pragma unroll
                for (int nn = 0; nn < 2; nn++) {
                    if (nn < njt) {
                        uint32_t bfr[2][4];
                        const uint32_t aB = buf + (uint32_t)((tj0 + nn) * 32) * ROWSTR + boff + koff;
                        ldsm4(bfr[0], aB);
                        ldsm4(bfr[1], aB + 16 * ROWSTR);
                        #pragma unroll
                        for (int mh = 0; mh < 2; mh++)
                            #pragma unroll
                            for (int nq = 0; nq < 4; nq++)
                                mma16816(acc[nn][mh][nq], afr[mh], &bfr[nq >> 1][(nq & 1) * 2]);
                    }
                }
            }

            // store batch A (to the OTHER buffer — safe), issue LDG batch B (it 4..6)
            float4 pfB[3];
            if (more) {
                #pragma unroll
                for (int it = 0; it < 4; it++)
                    sts_bf16(smem, nbuf, tid + it * NTHREADS, pfA[it]);
                #pragma unroll
                for (int it = 4; it < 7; it++) {
                    const int idx = tid + it * NTHREADS;
                    if (idx < 3200)
                        ldg128(pfB[it - 4], nb + (size_t)(idx >> 4) * HW + (idx & 15) * 4);
                }
            }

            // ---- ksteps 2,3 ----
            #pragma unroll
            for (int ks = 2; ks < 4; ks++) {
                const uint32_t koff = (uint32_t)ks * 32;
                uint32_t afr[2][4];
                ldsm4(afr[0], buf + arow + koff);
                ldsm4(afr[1], buf + arow + koff + 16 * ROWSTR);
                #pragma unroll
                for (int nn = 0; nn < 2; nn++) {
                    if (nn < njt) {
                        uint32_t bfr[2][4];
                        const uint32_t aB = buf + (uint32_t)((tj0 + nn) * 32) * ROWSTR + boff + koff;
                        ldsm4(bfr[0], aB);
                        ldsm4(bfr[1], aB + 16 * ROWSTR);
                        #pragma unroll
                        for (int mh = 0; mh < 2; mh++)
                            #pragma unroll
                            for (int nq = 0; nq < 4; nq++)
                                mma16816(acc[nn][mh][nq], afr[mh], &bfr[nq >> 1][(nq & 1) * 2]);
                    }
                }
            }

            // store batch B, then one sync to publish buf t+1 / retire buf t
            if (more) {
                #pragma unroll
                for (int it = 4; it < 7; it++) {
                    const int idx = tid + it * NTHREADS;
                    if (idx < 3200) sts_bf16(smem, nbuf, idx, pfB[it - 4]);
                }
                __syncthreads();
            }
        }

        // epilogue: u16 partials -> scratch (values <= 1792, exact; ti,tj <= 6 in-slab)
        #pragma unroll
        for (int nn = 0; nn < 2; nn++) {
            if (nn < njt) {
                unsigned short* dst = g_scratch16 + (size_t)bid * NPART
                                    + (size_t)(ti * 7 + (tj0 + nn)) * 1024;
                #pragma unroll
                for (int mh = 0; mh < 2; mh++) {
                    #pragma unroll
                    for (int nq = 0; nq < 4; nq++) {
                        const int r = mh * 16 + (lid >> 2);
                        const int c = nq * 8 + (lid & 3) * 2;
                        uint32_t w0 = (uint32_t)(int)acc[nn][mh][nq][0]
                                    | ((uint32_t)(int)acc[nn][mh][nq][1] << 16);
                        uint32_t w1 = (uint32_t)(int)acc[nn][mh][nq][2]
                                    | ((uint32_t)(int)acc[nn][mh][nq][3] << 16);
                        *reinterpret_cast<uint32_t*>(dst + (size_t)r * 32 + c) = w0;
                        *reinterpret_cast<uint32_t*>(dst + (size_t)(r + 8) * 32 + c) = w1;
                    }
                }
            }
        }
    }

    grid_barrier();

    // ================= phase 2: reduce u16 split-K partials =================
    // 448 jobs of 64 elements (32 u32 words); 2 warps/job (74 slabs each), smem combine.
    {
        int2* sred = reinterpret_cast<int2*>(smem);       // 256 int2
        const int gw = bid * 16 + wid;
        const int job = gw >> 1;
        const bool active = job < 448;
        int sa = 0, sb = 0;
        int e2 = 0;
        if (active) {
            e2 = (job << 6) + (lid << 1);                 // even element index
            const int tl = e2 >> 10;
            const int off = ((int)TIa[tl] * 7 + (int)TJa[tl]) * 1024 + (e2 & 1023);
            const unsigned short* p = g_scratch16 + (size_t)((gw & 1) * 74) * NPART + off;
            #pragma unroll
            for (int k = 0; k < 74; k++) {
                const uint32_t w = *reinterpret_cast<const uint32_t*>(p + (size_t)k * NPART);
                sa += (int)(w & 0xFFFFu);
                sb += (int)(w >> 16);
            }
        }
        if (active && (gw & 1)) sred[((wid >> 1) << 5) + lid] = make_int2(sa, sb);
        __syncthreads();
        if (active && !(gw & 1)) {
            const int2 o = sred[((wid >> 1) << 5) + lid];
            const int tl = e2 >> 10;
            const int gi = TIa[tl] * 32 + ((e2 >> 5) & 31);
            const int gj = TJa[tl] * 32 + (e2 & 31);
            if (gi < NR && gj < NR) {
                g_inter[gi * NR + gj] = (float)(sa + o.x);
                if (gj + 1 < NR) g_inter[gi * NR + gj + 1] = (float)(sb + o.y);
            }
        }
    }

    grid_barrier();

    // ================= phase 3a: compensate IoU, one warp per j =================
    {
        const int j = bid * 16 + wid;
        if (j < NR) {
            const int lj = labels[j];
            const float sj = g_inter[j * NR + j];
            float m = 0.f;
            for (int i = lid; i < j; i += 32) {
                if (labels[i] == lj) {
                    const float in_ = g_inter[i * NR + j];
                    m = fmaxf(m, in_ / (g_inter[i * NR + i] + sj - in_));
                }
            }
            #pragma unroll
            for (int o = 16; o; o >>= 1) m = fmaxf(m, __shfl_xor_sync(~0u, m, o));
            if (lid == 0) g_comp[j] = m;
        }
    }

    grid_barrier();

    // ================= phase 3b: decay coefficient (min over ALL i) =================
    {
        const int j = bid * 16 + wid;
        if (j < NR) {
            const int lj = labels[j];
            const float sj = g_inter[j * NR + j];
            float mn = 3.4e38f;
            for (int i = lid; i < NR; i += 32) {
                float d = 0.f;
                if (i < j && labels[i] == lj) {
                    const float in_ = g_inter[i * NR + j];
                    d = in_ / (g_inter[i * NR + i] + sj - in_);
                }
                const float c = g_comp[i];
                mn = fminf(mn, c * c - d * d);
            }
            #pragma unroll
            for (int o = 16; o; o >>= 1) mn = fminf(mn, __shfl_xor_sync(~0u, mn, o));
            if (lid == 0) out[j] = scores[j] * expf(2.0f * mn);   // SIGMA = 2
        }
    }
}

// ============================ launch ============================
extern "C" void kernel_launch(void* const* d_in, const int* in_sizes, int n_in,
                              void* d_out, int out_size) {
    const float* seg    = (const float*)d_in[0];
    const float* scores = (const float*)d_in[1];
    const int*   labels = (const int*)d_in[2];
    float* out = (float*)d_out;

    cudaFuncSetAttribute(fused_kernel, cudaFuncAttributeMaxDynamicSharedMemorySize, DYN_SMEM);
    fused_kernel<<<GRID, NTHREADS, DYN_SMEM>>>(seg, scores, labels, out);
}

// round 11
// speedup vs baseline: 1.2117x; 1.2117x over previous
#include <cuda_runtime.h>
#include <cuda_bf16.h>
#include <cstdint>

// ============================ constants ============================
#define NR        200               // number of masks
#define HW        200704            // 448*448
#define NTK       3136              // total K tiles of 64
#define GRID      148
#define NTHREADS  512
#define ROWSTR    144               // bf16 buffer row stride (conflict-free for LDSM)
#define STAGE_B   51200             // 200 rows * 64 fp32
#define BUF_B     (224*ROWSTR)      // 32256 (200 data rows + 24 zero pad)
#define OFF_BUF   (2*STAGE_B)       // 102400
#define DYN_SMEM  (2*STAGE_B + 4*BUF_B)   // 231424 (fits 227KB opt-in)
#define NTOUT     28                // upper-tri 32x32 tiles (7x7 grid)
#define NPART     (49*1024)         // slab elements (full 7x7 grid)

__device__ unsigned short g_scratch16[(size_t)GRID * NPART];   // u16 partials (<=1792, exact)
__device__ float g_inter[NR * NR];
__device__ float g_comp[256];
__device__ unsigned g_count;
__device__ unsigned g_gen;

__device__ __constant__ unsigned char TIa[NTOUT] =
    {0,0,0,0,0,0,0, 1,1,1,1,1,1, 2,2,2,2,2, 3,3,3,3, 4,4,4, 5,5, 6};
__device__ __constant__ unsigned char TJa[NTOUT] =
    {0,1,2,3,4,5,6, 1,2,3,4,5,6, 2,3,4,5,6, 3,4,5,6, 4,5,6, 5,6, 6};

// per-warp gram jobs: 12 pairs (A-fragment shared across 2 tj) + 4 singles = 16 (proven)
__device__ __constant__ unsigned char JTI[16] = {0,0,0, 1,1,1, 2,2, 3,3, 4, 5, 0, 2, 4, 6};
__device__ __constant__ unsigned char JT0[16] = {0,2,4, 1,3,5, 2,4, 3,5, 4, 5, 6, 6, 6, 6};
__device__ __constant__ unsigned char JN [16] = {2,2,2, 2,2,2, 2,2, 2,2, 2, 2, 1, 1, 1, 1};

// ============================ helpers ============================
__device__ __forceinline__ uint32_t smem_u32(const void* p) {
    uint32_t a;
    asm("{ .reg .u64 t; cvta.to.shared.u64 t, %1; cvt.u32.u64 %0, t; }"
        : "=r"(a) : "l"(p));
    return a;
}

__device__ __forceinline__ void cp_async16(uint32_t sdst, const void* gsrc) {
    asm volatile("cp.async.cg.shared.global [%0], [%1], 16;"
                 :: "r"(sdst), "l"(gsrc) : "memory");
}
#define CP_COMMIT() asm volatile("cp.async.commit_group;" ::: "memory")
#define CP_WAIT0()  asm volatile("cp.async.wait_group 0;" ::: "memory")

__device__ __forceinline__ void ldsm4(uint32_t* r, uint32_t addr) {
    asm volatile("ldmatrix.sync.aligned.m8n8.x4.shared.b16 {%0,%1,%2,%3}, [%4];"
                 : "=r"(r[0]), "=r"(r[1]), "=r"(r[2]), "=r"(r[3]) : "r"(addr));
}

__device__ __forceinline__ void mma16816(float* d, const uint32_t* a, const uint32_t* b) {
    asm volatile(
        "mma.sync.aligned.m16n8k16.row.col.f32.bf16.bf16.f32 "
        "{%0,%1,%2,%3}, {%4,%5,%6,%7}, {%8,%9}, {%0,%1,%2,%3};"
        : "+f"(d[0]), "+f"(d[1]), "+f"(d[2]), "+f"(d[3])
        : "r"(a[0]), "r"(a[1]), "r"(a[2]), "r"(a[3]), "r"(b[0]), "r"(b[1]));
}

// grid barrier: atomic arrivals, plain-load polling with nanosleep backoff
__device__ __forceinline__ void grid_barrier() {
    __syncthreads();
    if (threadIdx.x == 0) {
        __threadfence();
        unsigned gen = *(volatile unsigned*)&g_gen;
        unsigned arrived = atomicAdd(&g_count, 1u) + 1u;
        if (arrived == GRID) {
            atomicExch(&g_count, 0u);
            __threadfence();
            atomicAdd(&g_gen, 1u);
        } else {
            while (*(volatile unsigned*)&g_gen == gen) __nanosleep(128);
        }
        __threadfence();
    }
    __syncthreads();
}

__device__ __forceinline__ void issue_stage(uint32_t stage, const float* seg, int t, int tid) {
    const float* base = seg + (size_t)t * 64;
    #pragma unroll
    for (int it = 0; it < 6; it++) {
        int idx = tid + it * NTHREADS;
        int row = idx >> 4, c4 = idx & 15;
        cp_async16(stage + (uint32_t)idx * 16, base + (size_t)row * HW + c4 * 4);
    }
    if (tid < 128) {
        int idx = tid + 3072;
        int row = idx >> 4, c4 = idx & 15;
        cp_async16(stage + (uint32_t)idx * 16, base + (size_t)row * HW + c4 * 4);
    }
    CP_COMMIT();
}

__device__ __forceinline__ void convert_stage(char* smem, int stage_off, int buf_off, int tid) {
    #pragma unroll
    for (int it = 0; it < 7; it++) {
        int idx = tid + it * NTHREADS;
        if (idx < 3200) {
            int row = idx >> 4, c4 = idx & 15;
            float4 v = *reinterpret_cast<const float4*>(smem + stage_off + (size_t)idx * 16);
            __nv_bfloat162 p0 = __floats2bfloat162_rn(v.x, v.y);
            __nv_bfloat162 p1 = __floats2bfloat162_rn(v.z, v.w);
            uint2 w;
            w.x = *reinterpret_cast<uint32_t*>(&p0);
            w.y = *reinterpret_cast<uint32_t*>(&p1);
            *reinterpret_cast<uint2*>(smem + buf_off + (size_t)row * ROWSTR + c4 * 8) = w;
        }
    }
}

// one 64-K tile of MMA work for this warp's job (4 ksteps)
__device__ __forceinline__ void compute_tile(uint32_t buf, uint32_t arow, uint32_t boff,
                                             int tj0, int njt,
                                             float acc[2][2][4][4]) {
    #pragma unroll
    for (int ks = 0; ks < 4; ks++) {
        const uint32_t koff = (uint32_t)ks * 32;   // 16 bf16 = 32 bytes
        uint32_t afr[2][4];
        ldsm4(afr[0], buf + arow + koff);
        ldsm4(afr[1], buf + arow + koff + 16 * ROWSTR);
        #pragma unroll
        for (int nn = 0; nn < 2; nn++) {
            if (nn < njt) {
                uint32_t bfr[2][4];
                const uint32_t aB = buf + (uint32_t)((tj0 + nn) * 32) * ROWSTR + boff + koff;
                ldsm4(bfr[0], aB);
                ldsm4(bfr[1], aB + 16 * ROWSTR);
                #pragma unroll
                for (int mh = 0; mh < 2; mh++)
                    #pragma unroll
                    for (int nq = 0; nq < 4; nq++)
                        mma16816(acc[nn][mh][nq], afr[mh], &bfr[nq >> 1][(nq & 1) * 2]);
            }
        }
    }
}

// ============================ fused kernel ============================
__global__ __launch_bounds__(NTHREADS, 1)
void fused_kernel(const float* __restrict__ seg,
                  const float* __restrict__ scores,
                  const int* __restrict__ labels,
                  float* __restrict__ out) {
    extern __shared__ char smem[];
    const uint32_t sbase = smem_u32(smem);
    const int tid = threadIdx.x;
    const int wid = tid >> 5;
    const int lid = tid & 31;
    const int bid = blockIdx.x;

    // ================= phase 1: split-K Gram (bf16 mma, 2 tiles per sync) =================
    {
        const int t0 = (bid * NTK) / GRID;
        const int t1 = ((bid + 1) * NTK) / GRID;

        // zero pad rows 200..223 of all 4 bf16 buffers (written once)
        for (int i = tid; i < (24 * ROWSTR) / 4; i += NTHREADS) {
            #pragma unroll
            for (int b = 0; b < 4; b++)
                *reinterpret_cast<uint32_t*>(smem + OFF_BUF + b * BUF_B + 200 * ROWSTR + i * 4) = 0u;
        }

        const int ti  = JTI[wid];
        const int tj0 = JT0[wid];
        const int njt = JN[wid];

        float acc[2][2][4][4];   // [tile][m-half][n-quarter][regs]
        #pragma unroll
        for (int a = 0; a < 2; a++)
            #pragma unroll
            for (int b = 0; b < 2; b++)
                #pragma unroll
                for (int c = 0; c < 4; c++)
                    #pragma unroll
                    for (int d = 0; d < 4; d++) acc[a][b][c][d] = 0.f;

        const uint32_t aoff = (uint32_t)(lid & 15) * ROWSTR + (uint32_t)((lid >> 4) << 4);
        const uint32_t boff = (uint32_t)(((lid >> 4) << 3) + (lid & 7)) * ROWSTR
                            + (uint32_t)(((lid >> 3) & 1) << 4);
        const uint32_t arow = (uint32_t)(ti * 32) * ROWSTR + aoff;

        // prologue: stage + convert tiles t0 (and t0+1)
        issue_stage(sbase, seg, t0, tid);
        if (t0 + 1 < t1) issue_stage(sbase + STAGE_B, seg, t0 + 1, tid);
        CP_WAIT0();
        convert_stage(smem, 0, OFF_BUF + (t0 & 3) * BUF_B, tid);
        if (t0 + 1 < t1) convert_stage(smem, STAGE_B, OFF_BUF + ((t0 + 1) & 3) * BUF_B, tid);
        __syncthreads();

        int t = t0;
        for (; t + 1 < t1; t += 2) {
            // prefetch pair t+2, t+3
            const bool n0 = (t + 2 < t1);
            const bool n1 = (t + 3 < t1);
            if (n0) issue_stage(sbase, seg, t + 2, tid);
            if (n1) issue_stage(sbase + STAGE_B, seg, t + 3, tid);

            // compute tiles t and t+1 (8 uninterrupted ksteps)
            compute_tile(sbase + OFF_BUF + (uint32_t)((t & 3) * BUF_B), arow, boff, tj0, njt, acc);
            compute_tile(sbase + OFF_BUF + (uint32_t)(((t + 1) & 3) * BUF_B), arow, boff, tj0, njt, acc);

            if (n0) {
                CP_WAIT0();
                convert_stage(smem, 0, OFF_BUF + ((t + 2) & 3) * BUF_B, tid);
                if (n1) convert_stage(smem, STAGE_B, OFF_BUF + ((t + 3) & 3) * BUF_B, tid);
                __syncthreads();
            }
        }
        // odd tail tile
        if (t < t1)
            compute_tile(sbase + OFF_BUF + (uint32_t)((t & 3) * BUF_B), arow, boff, tj0, njt, acc);

        // epilogue: u16 partials -> scratch (values <= 1792, exact)
        #pragma unroll
        for (int nn = 0; nn < 2; nn++) {
            if (nn < njt) {
                unsigned short* dst = g_scratch16 + (size_t)bid * NPART
                                    + (size_t)(ti * 7 + (tj0 + nn)) * 1024;
                #pragma unroll
                for (int mh = 0; mh < 2; mh++) {
                    #pragma unroll
                    for (int nq = 0; nq < 4; nq++) {
                        const int r = mh * 16 + (lid >> 2);
                        const int c = nq * 8 + (lid & 3) * 2;
                        uint32_t w0 = (uint32_t)(int)acc[nn][mh][nq][0]
                                    | ((uint32_t)(int)acc[nn][mh][nq][1] << 16);
                        uint32_t w1 = (uint32_t)(int)acc[nn][mh][nq][2]
                                    | ((uint32_t)(int)acc[nn][mh][nq][3] << 16);
                        *reinterpret_cast<uint32_t*>(dst + (size_t)r * 32 + c) = w0;
                        *reinterpret_cast<uint32_t*>(dst + (size_t)(r + 8) * 32 + c) = w1;
                    }
                }
            }
        }
    }

    grid_barrier();

    // ================= phase 2: reduce u16 split-K partials =================
    // 448 jobs of 64 elements (32 u32 words); 2 warps/job (74 slabs each), smem combine.
    {
        int2* sred = reinterpret_cast<int2*>(smem);       // 256 int2
        const int gw = bid * 16 + wid;
        const int job = gw >> 1;
        const bool active = job < 448;
        int sa = 0, sb = 0;
        int e2 = 0;
        if (active) {
            e2 = (job << 6) + (lid << 1);                 // even element index
            const int tl = e2 >> 10;
            const int off = ((int)TIa[tl] * 7 + (int)TJa[tl]) * 1024 + (e2 & 1023);
            const unsigned short* p = g_scratch16 + (size_t)((gw & 1) * 74) * NPART + off;
            #pragma unroll
            for (int k = 0; k < 74; k++) {
                const uint32_t w = *reinterpret_cast<const uint32_t*>(p + (size_t)k * NPART);
                sa += (int)(w & 0xFFFFu);
                sb += (int)(w >> 16);
            }
        }
        if (active && (gw & 1)) sred[((wid >> 1) << 5) + lid] = make_int2(sa, sb);
        __syncthreads();
        if (active && !(gw & 1)) {
            const int2 o = sred[((wid >> 1) << 5) + lid];
            const int tl = e2 >> 10;
            const int gi = TIa[tl] * 32 + ((e2 >> 5) & 31);
            const int gj = TJa[tl] * 32 + (e2 & 31);
            if (gi < NR && gj < NR) {
                g_inter[gi * NR + gj] = (float)(sa + o.x);
                if (gj + 1 < NR) g_inter[gi * NR + gj + 1] = (float)(sb + o.y);
            }
        }
    }

    grid_barrier();

    // ================= phase 3a: compensate IoU, one warp per j =================
    {
        const int j = bid * 16 + wid;
        if (j < NR) {
            const int lj = labels[j];
            const float sj = g_inter[j * NR + j];
            float m = 0.f;
            for (int i = lid; i < j; i += 32) {
                if (labels[i] == lj) {
                    const float in_ = g_inter[i * NR + j];
                    m = fmaxf(m, in_ / (g_inter[i * NR + i] + sj - in_));
                }
            }
            #pragma unroll
            for (int o = 16; o; o >>= 1) m = fmaxf(m, __shfl_xor_sync(~0u, m, o));
            if (lid == 0) g_comp[j] = m;
        }
    }

    grid_barrier();

    // ================= phase 3b: decay coefficient (min over ALL i) =================
    {
        const int j = bid * 16 + wid;
        if (j < NR) {
            const int lj = labels[j];
            const float sj = g_inter[j * NR + j];
            float mn = 3.4e38f;
            for (int i = lid; i < NR; i += 32) {
                float d = 0.f;
                if (i < j && labels[i] == lj) {
                    const float in_ = g_inter[i * NR + j];
                    d = in_ / (g_inter[i * NR + i] + sj - in_);
                }
                const float c = g_comp[i];
                mn = fminf(mn, c * c - d * d);
            }
            #pragma unroll
            for (int o = 16; o; o >>= 1) mn = fminf(mn, __shfl_xor_sync(~0u, mn, o));
            if (lid == 0) out[j] = scores[j] * expf(2.0f * mn);   // SIGMA = 2
        }
    }
}

// ============================ launch ============================
extern "C" void kernel_launch(void* const* d_in, const int* in_sizes, int n_in,
                              void* d_out, int out_size) {
    const float* seg    = (const float*)d_in[0];
    const float* scores = (const float*)d_in[1];
    const int*   labels = (const int*)d_in[2];
    float* out = (float*)d_out;

    cudaFuncSetAttribute(fused_kernel, cudaFuncAttributeMaxDynamicSharedMemorySize, DYN_SMEM);
    fused_kernel<<<GRID, NTHREADS, DYN_SMEM>>>(seg, scores, labels, out);
}

// round 12
// speedup vs baseline: 1.2569x; 1.0373x over previous
#include <cuda_runtime.h>
#include <cuda_bf16.h>
#include <cstdint>

// ============================ constants ============================
#define NR        200               // number of masks
#define HW        200704            // 448*448
#define NTK       3136              // total K tiles of 64
#define GRID      148
#define NTHREADS  512
#define ROWSTR    144               // bf16 buffer row stride (conflict-free for LDSM)
#define STAGE_B   51200             // 200 rows * 64 fp32
#define BUF_B     (224*ROWSTR)      // 32256 (200 data rows + 24 zero pad)
#define OFF_BUF   (2*STAGE_B)       // 102400
#define DYN_SMEM  (2*STAGE_B + 4*BUF_B)   // 231424
#define NTOUT     28                // upper-tri 32x32 tiles (7x7 grid)
#define NPART     (49*1024)         // slab elements (full 7x7 grid)

__device__ unsigned short g_scratch16[(size_t)GRID * NPART];   // u16 partials (<=1792, exact)
__device__ float g_inter[NR * NR];
__device__ float g_comp[256];
__device__ unsigned g_count;
__device__ unsigned g_gen;

__device__ __constant__ unsigned char TIa[NTOUT] =
    {0,0,0,0,0,0,0, 1,1,1,1,1,1, 2,2,2,2,2, 3,3,3,3, 4,4,4, 5,5, 6};
__device__ __constant__ unsigned char TJa[NTOUT] =
    {0,1,2,3,4,5,6, 1,2,3,4,5,6, 2,3,4,5,6, 3,4,5,6, 4,5,6, 5,6, 6};

// per-warp gram jobs: 12 pairs (A-fragment shared across 2 tj) + 4 singles = 16 (proven)
__device__ __constant__ unsigned char JTI[16] = {0,0,0, 1,1,1, 2,2, 3,3, 4, 5, 0, 2, 4, 6};
__device__ __constant__ unsigned char JT0[16] = {0,2,4, 1,3,5, 2,4, 3,5, 4, 5, 6, 6, 6, 6};
__device__ __constant__ unsigned char JN [16] = {2,2,2, 2,2,2, 2,2, 2,2, 2, 2, 1, 1, 1, 1};

// ============================ helpers ============================
__device__ __forceinline__ uint32_t smem_u32(const void* p) {
    uint32_t a;
    asm("{ .reg .u64 t; cvta.to.shared.u64 t, %1; cvt.u32.u64 %0, t; }"
        : "=r"(a) : "l"(p));
    return a;
}

__device__ __forceinline__ void cp_async16(uint32_t sdst, const void* gsrc) {
    asm volatile("cp.async.cg.shared.global [%0], [%1], 16;"
                 :: "r"(sdst), "l"(gsrc) : "memory");
}
#define CP_COMMIT() asm volatile("cp.async.commit_group;" ::: "memory")
#define CP_WAIT0()  asm volatile("cp.async.wait_group 0;" ::: "memory")

__device__ __forceinline__ void ldsm4(uint32_t* r, uint32_t addr) {
    asm volatile("ldmatrix.sync.aligned.m8n8.x4.shared.b16 {%0,%1,%2,%3}, [%4];"
                 : "=r"(r[0]), "=r"(r[1]), "=r"(r[2]), "=r"(r[3]) : "r"(addr));
}

__device__ __forceinline__ void mma16816(float* d, const uint32_t* a, const uint32_t* b) {
    asm volatile(
        "mma.sync.aligned.m16n8k16.row.col.f32.bf16.bf16.f32 "
        "{%0,%1,%2,%3}, {%4,%5,%6,%7}, {%8,%9}, {%0,%1,%2,%3};"
        : "+f"(d[0]), "+f"(d[1]), "+f"(d[2]), "+f"(d[3])
        : "r"(a[0]), "r"(a[1]), "r"(a[2]), "r"(a[3]), "r"(b[0]), "r"(b[1]));
}

// grid barrier: atomic arrivals, plain-load polling with nanosleep backoff
__device__ __forceinline__ void grid_barrier() {
    __syncthreads();
    if (threadIdx.x == 0) {
        __threadfence();
        unsigned gen = *(volatile unsigned*)&g_gen;
        unsigned arrived = atomicAdd(&g_count, 1u) + 1u;
        if (arrived == GRID) {
            atomicExch(&g_count, 0u);
            __threadfence();
            atomicAdd(&g_gen, 1u);
        } else {
            while (*(volatile unsigned*)&g_gen == gen) __nanosleep(128);
        }
        __threadfence();
    }
    __syncthreads();
}

__device__ __forceinline__ void issue_stage(uint32_t stage, const float* seg, int t, int tid) {
    const float* base = seg + (size_t)t * 64;
    #pragma unroll
    for (int it = 0; it < 6; it++) {
        int idx = tid + it * NTHREADS;
        int row = idx >> 4, c4 = idx & 15;
        cp_async16(stage + (uint32_t)idx * 16, base + (size_t)row * HW + c4 * 4);
    }
    if (tid < 128) {
        int idx = tid + 3072;
        int row = idx >> 4, c4 = idx & 15;
        cp_async16(stage + (uint32_t)idx * 16, base + (size_t)row * HW + c4 * 4);
    }
    CP_COMMIT();
}

__device__ __forceinline__ void convert_stage(char* smem, int stage_off, int buf_off, int tid) {
    #pragma unroll
    for (int it = 0; it < 7; it++) {
        int idx = tid + it * NTHREADS;
        if (idx < 3200) {
            int row = idx >> 4, c4 = idx & 15;
            float4 v = *reinterpret_cast<const float4*>(smem + stage_off + (size_t)idx * 16);
            __nv_bfloat162 p0 = __floats2bfloat162_rn(v.x, v.y);
            __nv_bfloat162 p1 = __floats2bfloat162_rn(v.z, v.w);
            uint2 w;
            w.x = *reinterpret_cast<uint32_t*>(&p0);
            w.y = *reinterpret_cast<uint32_t*>(&p1);
            *reinterpret_cast<uint2*>(smem + buf_off + (size_t)row * ROWSTR + c4 * 8) = w;
        }
    }
}

// one 64-K tile of MMA work; REV=1 traverses ksteps in reverse (commutative)
template<int REV>
__device__ __forceinline__ void compute_tile(uint32_t buf, uint32_t arow, uint32_t boff,
                                             int tj0, int njt,
                                             float acc[2][2][4][4]) {
    #pragma unroll
    for (int s = 0; s < 4; s++) {
        const int ks = REV ? (3 - s) : s;
        const uint32_t koff = (uint32_t)ks * 32;   // 16 bf16 = 32 bytes
        uint32_t afr[2][4];
        ldsm4(afr[0], buf + arow + koff);
        ldsm4(afr[1], buf + arow + koff + 16 * ROWSTR);
        #pragma unroll
        for (int nn = 0; nn < 2; nn++) {
            if (nn < njt) {
                uint32_t bfr[2][4];
                const uint32_t aB = buf + (uint32_t)((tj0 + nn) * 32) * ROWSTR + boff + koff;
                ldsm4(bfr[0], aB);
                ldsm4(bfr[1], aB + 16 * ROWSTR);
                #pragma unroll
                for (int mh = 0; mh < 2; mh++)
                    #pragma unroll
                    for (int nq = 0; nq < 4; nq++)
                        mma16816(acc[nn][mh][nq], afr[mh], &bfr[nq >> 1][(nq & 1) * 2]);
            }
        }
    }
}

// ============================ fused kernel ============================
__global__ __launch_bounds__(NTHREADS, 1)
void fused_kernel(const float* __restrict__ seg,
                  const float* __restrict__ scores,
                  const int* __restrict__ labels,
                  float* __restrict__ out) {
    extern __shared__ char smem[];
    const uint32_t sbase = smem_u32(smem);
    const int tid = threadIdx.x;
    const int wid = tid >> 5;
    const int lid = tid & 31;
    const int bid = blockIdx.x;

    // ================= phase 1: split-K Gram (bf16 mma, warp-staggered) =================
    {
        const int t0 = (bid * NTK) / GRID;
        const int t1 = ((bid + 1) * NTK) / GRID;

        // zero pad rows 200..223 of all 4 bf16 buffers (written once)
        for (int i = tid; i < (24 * ROWSTR) / 4; i += NTHREADS) {
            #pragma unroll
            for (int b = 0; b < 4; b++)
                *reinterpret_cast<uint32_t*>(smem + OFF_BUF + b * BUF_B + 200 * ROWSTR + i * 4) = 0u;
        }

        const int ti  = JTI[wid];
        const int tj0 = JT0[wid];
        const int njt = JN[wid];
        const bool odd = (wid & 1);

        float acc[2][2][4][4];   // [tile][m-half][n-quarter][regs]
        #pragma unroll
        for (int a = 0; a < 2; a++)
            #pragma unroll
            for (int b = 0; b < 2; b++)
                #pragma unroll
                for (int c = 0; c < 4; c++)
                    #pragma unroll
                    for (int d = 0; d < 4; d++) acc[a][b][c][d] = 0.f;

        const uint32_t aoff = (uint32_t)(lid & 15) * ROWSTR + (uint32_t)((lid >> 4) << 4);
        const uint32_t boff = (uint32_t)(((lid >> 4) << 3) + (lid & 7)) * ROWSTR
                            + (uint32_t)(((lid >> 3) & 1) << 4);
        const uint32_t arow = (uint32_t)(ti * 32) * ROWSTR + aoff;

        // prologue: stage + convert tiles t0 (and t0+1)
        issue_stage(sbase, seg, t0, tid);
        if (t0 + 1 < t1) issue_stage(sbase + STAGE_B, seg, t0 + 1, tid);
        CP_WAIT0();
        convert_stage(smem, 0, OFF_BUF + (t0 & 3) * BUF_B, tid);
        if (t0 + 1 < t1) convert_stage(smem, STAGE_B, OFF_BUF + ((t0 + 1) & 3) * BUF_B, tid);
        __syncthreads();

        int t = t0;
        for (; t + 1 < t1; t += 2) {
            // prefetch pair t+2, t+3
            const bool n0 = (t + 2 < t1);
            const bool n1 = (t + 3 < t1);
            if (n0) issue_stage(sbase, seg, t + 2, tid);
            if (n1) issue_stage(sbase + STAGE_B, seg, t + 3, tid);

            const uint32_t bufE = sbase + OFF_BUF + (uint32_t)((t & 3) * BUF_B);
            const uint32_t bufO = sbase + OFF_BUF + (uint32_t)(((t + 1) & 3) * BUF_B);

            // staggered: even warps t(fwd) then t+1(fwd); odd warps t+1(rev) then t(rev)
            if (!odd) {
                compute_tile<0>(bufE, arow, boff, tj0, njt, acc);
                compute_tile<0>(bufO, arow, boff, tj0, njt, acc);
            } else {
                compute_tile<1>(bufO, arow, boff, tj0, njt, acc);
                compute_tile<1>(bufE, arow, boff, tj0, njt, acc);
            }

            if (n0) {
                CP_WAIT0();
                convert_stage(smem, 0, OFF_BUF + ((t + 2) & 3) * BUF_B, tid);
                if (n1) convert_stage(smem, STAGE_B, OFF_BUF + ((t + 3) & 3) * BUF_B, tid);
                __syncthreads();
            }
        }
        // odd tail tile
        if (t < t1) {
            const uint32_t buf = sbase + OFF_BUF + (uint32_t)((t & 3) * BUF_B);
            if (!odd) compute_tile<0>(buf, arow, boff, tj0, njt, acc);
            else      compute_tile<1>(buf, arow, boff, tj0, njt, acc);
        }

        // epilogue: u16 partials -> scratch (values <= 1792, exact)
        #pragma unroll
        for (int nn = 0; nn < 2; nn++) {
            if (nn < njt) {
                unsigned short* dst = g_scratch16 + (size_t)bid * NPART
                                    + (size_t)(ti * 7 + (tj0 + nn)) * 1024;
                #pragma unroll
                for (int mh = 0; mh < 2; mh++) {
                    #pragma unroll
                    for (int nq = 0; nq < 4; nq++) {
                        const int r = mh * 16 + (lid >> 2);
                        const int c = nq * 8 + (lid & 3) * 2;
                        uint32_t w0 = (uint32_t)(int)acc[nn][mh][nq][0]
                                    | ((uint32_t)(int)acc[nn][mh][nq][1] << 16);
                        uint32_t w1 = (uint32_t)(int)acc[nn][mh][nq][2]
                                    | ((uint32_t)(int)acc[nn][mh][nq][3] << 16);
                        *reinterpret_cast<uint32_t*>(dst + (size_t)r * 32 + c) = w0;
                        *reinterpret_cast<uint32_t*>(dst + (size_t)(r + 8) * 32 + c) = w1;
                    }
                }
            }
        }
    }

    grid_barrier();

    // ================= phase 2: reduce u16 split-K partials =================
    // 448 jobs of 64 elements (32 u32 words); 2 warps/job (74 slabs each), smem combine.
    {
        int2* sred = reinterpret_cast<int2*>(smem);       // 256 int2
        const int gw = bid * 16 + wid;
        const int job = gw >> 1;
        const bool active = job < 448;
        int sa = 0, sb = 0;
        int e2 = 0;
        if (active) {
            e2 = (job << 6) + (lid << 1);                 // even element index
            const int tl = e2 >> 10;
            const int off = ((int)TIa[tl] * 7 + (int)TJa[tl]) * 1024 + (e2 & 1023);
            const unsigned short* p = g_scratch16 + (size_t)((gw & 1) * 74) * NPART + off;
            #pragma unroll
            for (int k = 0; k < 74; k++) {
                const uint32_t w = *reinterpret_cast<const uint32_t*>(p + (size_t)k * NPART);
                sa += (int)(w & 0xFFFFu);
                sb += (int)(w >> 16);
            }
        }
        if (active && (gw & 1)) sred[((wid >> 1) << 5) + lid] = make_int2(sa, sb);
        __syncthreads();
        if (active && !(gw & 1)) {
            const int2 o = sred[((wid >> 1) << 5) + lid];
            const int tl = e2 >> 10;
            const int gi = TIa[tl] * 32 + ((e2 >> 5) & 31);
            const int gj = TJa[tl] * 32 + (e2 & 31);
            if (gi < NR && gj < NR) {
                g_inter[gi * NR + gj] = (float)(sa + o.x);
                if (gj + 1 < NR) g_inter[gi * NR + gj + 1] = (float)(sb + o.y);
            }
        }
    }

    grid_barrier();

    // ================= phase 3a: compensate IoU, one warp per j =================
    {
        const int j = bid * 16 + wid;
        if (j < NR) {
            const int lj = labels[j];
            const float sj = g_inter[j * NR + j];
            float m = 0.f;
            for (int i = lid; i < j; i += 32) {
                if (labels[i] == lj) {
                    const float in_ = g_inter[i * NR + j];
                    m = fmaxf(m, in_ / (g_inter[i * NR + i] + sj - in_));
                }
            }
            #pragma unroll
            for (int o = 16; o; o >>= 1) m = fmaxf(m, __shfl_xor_sync(~0u, m, o));
            if (lid == 0) g_comp[j] = m;
        }
    }

    grid_barrier();

    // ================= phase 3b: decay coefficient (min over ALL i) =================
    {
        const int j = bid * 16 + wid;
        if (j < NR) {
            const int lj = labels[j];
            const float sj = g_inter[j * NR + j];
            float mn = 3.4e38f;
            for (int i = lid; i < NR; i += 32) {
                float d = 0.f;
                if (i < j && labels[i] == lj) {
                    const float in_ = g_inter[i * NR + j];
                    d = in_ / (g_inter[i * NR + i] + sj - in_);
                }
                const float c = g_comp[i];
                mn = fminf(mn, c * c - d * d);
            }
            #pragma unroll
            for (int o = 16; o; o >>= 1) mn = fminf(mn, __shfl_xor_sync(~0u, mn, o));
            if (lid == 0) out[j] = scores[j] * expf(2.0f * mn);   // SIGMA = 2
        }
    }
}

// ============================ launch ============================
extern "C" void kernel_launch(void* const* d_in, const int* in_sizes, int n_in,
                              void* d_out, int out_size) {
    const float* seg    = (const float*)d_in[0];
    const float* scores = (const float*)d_in[1];
    const int*   labels = (const int*)d_in[2];
    float* out = (float*)d_out;

    cudaFuncSetAttribute(fused_kernel, cudaFuncAttributeMaxDynamicSharedMemorySize, DYN_SMEM);
    fused_kernel<<<GRID, NTHREADS, DYN_SMEM>>>(seg, scores, labels, out);
}